// round 15
// baseline (speedup 1.0000x reference)
#include <cuda_runtime.h>
#include <cstdint>

#define VOCAB 32000
#define BOS_ID 1
#define BSZ 8
#define SEQLEN 2048

#define ROW4 (VOCAB / 4)          // 8000 float4 per (b,s) row
#define BLOCKS_PER_B 8000         // fill blocks per batch row (window = 2048 float4)

// Per-row majority token, computed by hist_kernel, consumed by fill_kernel.
__device__ int g_pred[BSZ];

// ---------------------------------------------------------------------------
// Kernel 1: per-row majority, minimal latency.
//  - No full-histogram zero: only slots of PRESENT tokens are ever read, so
//    each thread zeroes just its own 2 token slots (duplicates benign).
//  - Argmax reads counts[] only at those same 2 positions.
//  - Triggers PDL completion at entry (8 blocks -> downstream launches now).
// ---------------------------------------------------------------------------
__global__ void __launch_bounds__(1024) hist_kernel(const int* __restrict__ ids) {
    cudaTriggerProgrammaticLaunchCompletion();

    extern __shared__ int counts[];
    __shared__ int warp_best[32];

    const int b = blockIdx.x;
    const int t = threadIdx.x;

    // Load this thread's 2 tokens first (global latency overlaps the rest).
    const int* row = ids + b * SEQLEN;
    const int v0 = row[t];
    const int v1 = row[t + 1024];
    const bool ok0 = (v0 > BOS_ID);           // valid <=> v!=0 && v!=1 <=> v>1
    const bool ok1 = (v1 > BOS_ID);

    // Zero ONLY the slots that will be used (<=2048 of 32000).
    if (ok0) counts[v0] = 0;
    if (ok1) counts[v1] = 0;
    __syncthreads();

    if (ok0) atomicAdd(&counts[v0], 1);
    if (ok1) atomicAdd(&counts[v1], 1);
    __syncthreads();

    // Packed key: (count << 15) | (0x7FFF - v). Higher count wins; equal
    // count -> lower v (argmax tie rule). count<=2048 (12b), v<32000 (15b).
    int best = 0;
    if (ok0) best = (counts[v0] << 15) | (0x7FFF - v0);
    if (ok1) best = max(best, (counts[v1] << 15) | (0x7FFF - v1));

    best = __reduce_max_sync(0xFFFFFFFFu, best);
    if ((t & 31) == 0) warp_best[t >> 5] = best;
    __syncthreads();

    if (t < 32) {
        int wb = __reduce_max_sync(0xFFFFFFFFu, warp_best[t]);
        if (t == 0) {
            int cnt = wb >> 15;
            g_pred[b] = (cnt > 0) ? (0x7FFF - (wb & 0x7FFF)) : BOS_ID;
        }
    }
}

// ---------------------------------------------------------------------------
// Kernel 2 (PDL downstream): stream 2.1 GB. griddepsync FIRST (pre-store wait
// is harmless; post-store work is what poisons the stream), then 8 STG.128
// per thread with all div/mod block-constant. Nothing after the stores.
// ---------------------------------------------------------------------------
__global__ void __launch_bounds__(256) fill_kernel(float4* __restrict__ out) {
    cudaGridDependencySynchronize();

    const int f = blockIdx.x;                 // window = 2048 float4 = 32KB
    const int t = threadIdx.x;

    const int b  = f / BLOCKS_PER_B;          // block-constant magic-div
    const int c0 = ((f % BLOCKS_PER_B) * 2048) % ROW4;  // start col of window

    const int pred = g_pred[b];
    const int pc4  = pred >> 2;
    const int lane = pred & 3;

    float4* p = out + (long long)f * 2048 + t;
    #pragma unroll
    for (int j = 0; j < 8; j++) {
        int s = c0 + j * 256 + t;             // column within vocab row
        if (s >= ROW4) s -= ROW4;             // at most one wrap per window
        float4 val = make_float4(-6.0f, -6.0f, -6.0f, -6.0f);
        if (s == pc4) reinterpret_cast<float*>(&val)[lane] = 6.0f;
        p[j * 256] = val;
    }
}

// ---------------------------------------------------------------------------
extern "C" void kernel_launch(void* const* d_in, const int* in_sizes, int n_in,
                              void* d_out, int out_size) {
    (void)in_sizes; (void)n_in; (void)out_size;
    const int* ids = (const int*)d_in[0];

    const int smem_bytes = VOCAB * (int)sizeof(int);  // 128000 bytes
    cudaFuncSetAttribute(hist_kernel,
                         cudaFuncAttributeMaxDynamicSharedMemorySize, smem_bytes);

    hist_kernel<<<BSZ, 1024, smem_bytes>>>(ids);

    // Fill launched with PDL: may begin launching as soon as hist triggers;
    // the top-of-kernel griddepsync guards the g_pred read.
    cudaLaunchConfig_t cfg = {};
    cfg.gridDim = dim3(64000);
    cfg.blockDim = dim3(256);
    cfg.dynamicSmemBytes = 0;
    cfg.stream = 0;
    cudaLaunchAttribute attrs[1];
    attrs[0].id = cudaLaunchAttributeProgrammaticStreamSerialization;
    attrs[0].val.programmaticStreamSerializationAllowed = 1;
    cfg.attrs = attrs;
    cfg.numAttrs = 1;
    cudaLaunchKernelEx(&cfg, fill_kernel, (float4*)d_out);
}